// round 14
// baseline (speedup 1.0000x reference)
#include <cuda_runtime.h>
#include <math.h>
#include <stdint.h>

#define Tn 512
#define Bn 128
#define En 256
#define Hn 512
#define Vn 512
#define G4H 2048
#define TBr (Tn*Bn)     // 65536 rows (t*B + b)
#define BH  (Bn*Hn)     // 65536
#define NBLK 128

typedef unsigned long long ull;

// ---------------- packed f32x2 helpers ----------------------------------------
__device__ __forceinline__ ull dup2(float a) {
    ull r;
    asm("mov.b64 %0, {%1, %1};" : "=l"(r) : "f"(a));
    return r;
}
__device__ __forceinline__ void ffma2(ull& d, ull a, ull b) {
    asm("fma.rn.f32x2 %0, %1, %2, %0;" : "+l"(d) : "l"(a), "l"(b));
}
__device__ __forceinline__ float2 unpack2(ull v) {
    float2 r;
    asm("mov.b64 {%0, %1}, %2;" : "=f"(r.x), "=f"(r.y) : "l"(v));
    return r;
}

// ---------------- scratch (__device__ globals) --------------------------------
__device__ float g_e[(size_t)TBr * En];        // embeddings [T,B,E]
__device__ float g_li[(size_t)TBr * 2 * Hn];   // enc layer0 h history [T,B,2H]
__device__ float g_h1[(size_t)TBr * 2 * Hn];   // enc layer1 h history [T,B,2H]
__device__ float g_xpF[(size_t)TBr * G4H];     // x@Wx+bias, fwd
__device__ float g_xpB[(size_t)TBr * G4H];     // x@Wx+bias, bwd
__device__ float g_dh0[(size_t)TBr * Hn];      // decoder layer0 h history
__device__ float g_dechs[(size_t)TBr * Hn];    // decoder layer1 h history
__device__ float g_cfF[BH];                    // enc layer1 final c, fwd
__device__ float g_cfB[BH];                    // enc layer1 final c, bwd
__device__ float g_hb[BH];                     // bridge h init
__device__ float g_cb[BH];                     // bridge c init
__device__ unsigned g_ctr[4];                  // grid-barrier counters

// ---------------- grid barrier (release/acquire) ------------------------------
__device__ __forceinline__ void gsync(unsigned* ctr, unsigned target) {
    __threadfence();
    __syncthreads();
    if (threadIdx.x == 0) {
        asm volatile("red.release.gpu.global.add.u32 [%0], %1;"
                     :: "l"(ctr), "r"(1u) : "memory");
        unsigned v;
        do {
            asm volatile("ld.acquire.gpu.global.u32 %0, [%1];"
                         : "=r"(v) : "l"(ctr) : "memory");
            if (v >= target) break;
            __nanosleep(64);
        } while (true);
    }
    __syncthreads();
    __threadfence();
}

__global__ void reset_bar_kernel() {
    if (threadIdx.x < 4) g_ctr[threadIdx.x] = 0;
}

__device__ __forceinline__ float sigf(float x) { return 1.f / (1.f + expf(-x)); }

// ---------------- embedding (E = 256) -----------------------------------------
__global__ void embed_kernel(const int* __restrict__ x, const float* __restrict__ emb) {
    size_t idx = (size_t)blockIdx.x * blockDim.x + threadIdx.x;
    int r = (int)(idx >> 8);
    int c = (int)(idx & (En - 1));
    int t = r >> 7;
    int b = r & 127;
    int tok = x[b * Tn + t];
    g_e[idx] = emb[(size_t)tok * En + c];
}

// ---------------- 128x128 GEMM with packed f32x2 -------------------------------
// C[M,N] = A[M,K] @ W[K,N] + bias.  MAP==1: out row (b*Tn+t) reads A row (t*Bn+b).
template<int MAP>
__global__ __launch_bounds__(256) void gemm128(
    int M, int N, int K,
    const float* __restrict__ A, const float* __restrict__ W,
    const float* __restrict__ bias, float* __restrict__ C)
{
    __shared__ float As[8][128];
    __shared__ float Ws[8][128];
    const int bm = blockIdx.y * 128;
    const int bn = blockIdx.x * 128;
    const int tid = threadIdx.x;
    const int tr = tid / 16, tc = tid % 16;

    int crow = bm + tid / 2;
    int arow;
    if (MAP == 1) { int b = crow >> 9; int t = crow & (Tn - 1); arow = t * Bn + b; }
    else          { arow = crow; }
    const float* Aptr = A + (size_t)arow * K + (tid & 1) * 4;
    const float* Wptr = W + (size_t)(tid / 32) * N + bn + (tid & 31) * 4;

    ull acc[8][4];                        // 8 rows x 4 col-pairs (packed)
    #pragma unroll
    for (int i = 0; i < 8; i++)
        #pragma unroll
        for (int p = 0; p < 4; p++) acc[i][p] = 0ull;

    for (int k0 = 0; k0 < K; k0 += 8) {
        float4 a4 = *reinterpret_cast<const float4*>(Aptr + k0);
        float4 w4 = *reinterpret_cast<const float4*>(Wptr + (size_t)k0 * N);
        int ka = (tid & 1) * 4, ra = tid >> 1;
        As[ka + 0][ra] = a4.x; As[ka + 1][ra] = a4.y;
        As[ka + 2][ra] = a4.z; As[ka + 3][ra] = a4.w;
        *reinterpret_cast<float4*>(&Ws[tid / 32][(tid & 31) * 4]) = w4;
        __syncthreads();
        #pragma unroll
        for (int k = 0; k < 8; k++) {
            float4 a0 = *reinterpret_cast<float4*>(&As[k][tr * 8]);
            float4 a1 = *reinterpret_cast<float4*>(&As[k][tr * 8 + 4]);
            ulonglong2 w0 = *reinterpret_cast<ulonglong2*>(&Ws[k][tc * 8]);
            ulonglong2 w1 = *reinterpret_cast<ulonglong2*>(&Ws[k][tc * 8 + 4]);
            float av[8] = {a0.x, a0.y, a0.z, a0.w, a1.x, a1.y, a1.z, a1.w};
            ull wp[4] = {w0.x, w0.y, w1.x, w1.y};
            #pragma unroll
            for (int i = 0; i < 8; i++) {
                ull ad = dup2(av[i]);
                #pragma unroll
                for (int p = 0; p < 4; p++) ffma2(acc[i][p], ad, wp[p]);
            }
        }
        __syncthreads();
    }

    #pragma unroll
    for (int i = 0; i < 8; i++) {
        int row = bm + tr * 8 + i;
        float* Crow = C + (size_t)row * N + bn + tc * 8;
        float out[8];
        #pragma unroll
        for (int p = 0; p < 4; p++) {
            float2 v = unpack2(acc[i][p]);
            out[2 * p]     = v.x + bias[bn + tc * 8 + 2 * p];
            out[2 * p + 1] = v.y + bias[bn + tc * 8 + 2 * p + 1];
        }
        *reinterpret_cast<float4*>(Crow)     = make_float4(out[0], out[1], out[2], out[3]);
        *reinterpret_cast<float4*>(Crow + 4) = make_float4(out[4], out[5], out[6], out[7]);
    }
}

// ============ persistent encoder scan v2 (f32x2, 128 threads) =================
// 128 blocks: dir = bid&1, jt = bid>>1 (8 j's). Thread: ub=tid&31 (4 b's),
// uj=tid>>5 (2 j's x 4 gates). c register-resident; h via fresh history rows.
// smem: Wsm[512][32] interleaved (col = jj*4+g), Hsm[32][132] (k-major, b-contig)
template<bool CFIN>
__global__ __launch_bounds__(128) void enc_scan(
    const float* xpF, const float* xpB,
    const float* WhF, const float* WhB,
    float* hist, float* cfF, float* cfB, unsigned* ctr)
{
    extern __shared__ float sm[];
    float* Wsm = sm;                 // 16384 floats
    float* Hsm = sm + 16384;         // 32*132 floats
    const int tid = threadIdx.x;
    const int dir = blockIdx.x & 1;
    const int jt  = blockIdx.x >> 1;
    const int jb  = jt * 8;
    const int ub  = tid & 31;        // b-tile: b = ub*4 + i
    const int uj  = tid >> 5;        // j-pair: jj = 2*uj, 2*uj+1

    const float* Wh = dir ? WhB : WhF;
    const float* xp = dir ? xpB : xpF;
    float* cf = dir ? cfB : cfF;

    // Wsm[k*32 + jj*4 + g] = Wh[k][g*Hn + jb + jj]
    for (int i = tid; i < 16384; i += 128) {
        int k = i >> 5, col = i & 31, jj = col >> 2, g = col & 3;
        Wsm[i] = Wh[(size_t)k * G4H + g * Hn + jb + jj];
    }
    __syncthreads();

    const int j0 = jb + 2 * uj;      // this thread's two j's: j0, j0+1
    float cr[4][2];
    #pragma unroll
    for (int i = 0; i < 4; i++) { cr[i][0] = 0.f; cr[i][1] = 0.f; }

    unsigned phase = 0;

    for (int t = 0; t < Tn; t++) {
        const int tcur = dir ? (Tn - 1 - t) : t;
        ull acc[4][4];               // [b][j0g01, j0g23, j1g01, j1g23]
        #pragma unroll
        for (int i = 0; i < 4; i++)
            #pragma unroll
            for (int p = 0; p < 4; p++) acc[i][p] = 0ull;

        if (t > 0) {
            const int tprev = dir ? (tcur + 1) : (tcur - 1);
            const float* hp = hist + ((size_t)tprev * Bn) * (2 * Hn) + dir * Hn;
            for (int k0 = 0; k0 < Hn; k0 += 32) {
                // stage h[k][b] (transposed)
                for (int i2 = tid; i2 < 1024; i2 += 128) {
                    int b = i2 >> 3, q = i2 & 7;
                    float4 v = __ldcg(reinterpret_cast<const float4*>(
                        hp + (size_t)b * (2 * Hn) + k0 + q * 4));
                    Hsm[(q * 4 + 0) * 132 + b] = v.x;
                    Hsm[(q * 4 + 1) * 132 + b] = v.y;
                    Hsm[(q * 4 + 2) * 132 + b] = v.z;
                    Hsm[(q * 4 + 3) * 132 + b] = v.w;
                }
                __syncthreads();
                #pragma unroll 4
                for (int kk = 0; kk < 32; kk++) {
                    float4 h4 = *reinterpret_cast<float4*>(&Hsm[kk * 132 + ub * 4]);
                    ulonglong2 wA = *reinterpret_cast<ulonglong2*>(
                        &Wsm[(k0 + kk) * 32 + uj * 8]);
                    float hv[4] = {h4.x, h4.y, h4.z, h4.w};
                    #pragma unroll
                    for (int i = 0; i < 4; i++) {
                        ull hd = dup2(hv[i]);
                        ffma2(acc[i][0], hd, wA.x);
                        ffma2(acc[i][1], hd, wA.y);
                    }
                    ulonglong2 wB = *reinterpret_cast<ulonglong2*>(
                        &Wsm[(k0 + kk) * 32 + uj * 8 + 4]);
                    #pragma unroll
                    for (int i = 0; i < 4; i++) {
                        ull hd = dup2(hv[i]);
                        ffma2(acc[i][2], hd, wB.x);
                        ffma2(acc[i][3], hd, wB.y);
                    }
                }
                __syncthreads();
            }
        }

        #pragma unroll
        for (int i = 0; i < 4; i++) {
            int b = ub * 4 + i;
            const float* xr = xp + ((size_t)tcur * Bn + b) * G4H;
            #pragma unroll
            for (int jc = 0; jc < 2; jc++) {
                int j = j0 + jc;
                float2 gif = unpack2(acc[i][2 * jc]);       // (i, f)
                float2 ggo = unpack2(acc[i][2 * jc + 1]);   // (g, o)
                float gi = gif.x + xr[j];
                float gf = gif.y + xr[Hn + j];
                float gg = ggo.x + xr[2 * Hn + j];
                float go = ggo.y + xr[3 * Hn + j];
                float cn = sigf(gf) * cr[i][jc] + sigf(gi) * tanhf(gg);
                float hn = sigf(go) * tanhf(cn);
                cr[i][jc] = cn;
                __stcg(hist + ((size_t)tcur * Bn + b) * (2 * Hn) + dir * Hn + j, hn);
            }
        }
        if (t < Tn - 1) gsync(ctr, (++phase) * gridDim.x);
    }

    if (CFIN) {
        #pragma unroll
        for (int i = 0; i < 4; i++)
            #pragma unroll
            for (int jc = 0; jc < 2; jc++)
                cf[(size_t)(ub * 4 + i) * Hn + j0 + jc] = cr[i][jc];
    }
}

// ============ persistent decoder scan (unchanged from R13) ====================
__global__ __launch_bounds__(256) void dec_scan(
    const float* xp0, const float* Wh0, const float* Wx1,
    const float* Wh1, const float* b1, unsigned* ctr)
{
    extern __shared__ float sm[];
    float* W0  = sm;
    float* W1x = sm + 16384;
    float* W1h = sm + 32768;
    float* Hsm = sm + 49152;         // 64*33
    const int tid = threadIdx.x;
    const int bh = blockIdx.x & 1;
    const int jt = blockIdx.x >> 1;
    const int jb = jt * 8;
    const int jj = tid & 7;
    const int bq = tid >> 3;         // 0..31
    const int j  = jb + jj;

    for (int i = tid; i < 16384; i += 256) {
        int g = i >> 12, k = (i >> 3) & 511, j2 = i & 7;
        size_t off = (size_t)k * G4H + g * Hn + jb + j2;
        W0[i]  = Wh0[off];
        W1x[i] = Wx1[off];
        W1h[i] = Wh1[off];
    }
    float bias1g[4];
    #pragma unroll
    for (int g = 0; g < 4; g++) bias1g[g] = b1[g * Hn + j];
    __syncthreads();

    float c0r[2], c1r[2];
    #pragma unroll
    for (int i = 0; i < 2; i++) {
        int b = bh * 64 + bq * 2 + i;
        float cinit = g_cb[(size_t)b * Hn + j];
        c0r[i] = cinit;
        c1r[i] = cinit;
    }

    unsigned phase = 0;
    for (int t = 0; t < Tn; t++) {
        // ---- phase A: layer 0 ----
        {
            float acc[2][4] = {};
            const float* hbase = (t == 0) ? g_hb
                               : (g_dh0 + ((size_t)(t - 1) * Bn) * Hn);
            for (int k0 = 0; k0 < Hn; k0 += 32) {
                for (int i2 = tid; i2 < 512; i2 += 256) {
                    int bl = i2 >> 3, q = i2 & 7;
                    float4 v = __ldcg(reinterpret_cast<const float4*>(
                        hbase + (size_t)(bh * 64 + bl) * Hn + k0 + q * 4));
                    Hsm[bl * 33 + q * 4 + 0] = v.x;
                    Hsm[bl * 33 + q * 4 + 1] = v.y;
                    Hsm[bl * 33 + q * 4 + 2] = v.z;
                    Hsm[bl * 33 + q * 4 + 3] = v.w;
                }
                __syncthreads();
                #pragma unroll 8
                for (int kk = 0; kk < 32; kk++) {
                    float w0 = W0[0 * 4096 + (k0 + kk) * 8 + jj];
                    float w1 = W0[1 * 4096 + (k0 + kk) * 8 + jj];
                    float w2 = W0[2 * 4096 + (k0 + kk) * 8 + jj];
                    float w3 = W0[3 * 4096 + (k0 + kk) * 8 + jj];
                    #pragma unroll
                    for (int i = 0; i < 2; i++) {
                        float h = Hsm[(bq * 2 + i) * 33 + kk];
                        acc[i][0] += h * w0; acc[i][1] += h * w1;
                        acc[i][2] += h * w2; acc[i][3] += h * w3;
                    }
                }
                __syncthreads();
            }
            #pragma unroll
            for (int i = 0; i < 2; i++) {
                int b = bh * 64 + bq * 2 + i;
                const float* xr = xp0 + ((size_t)t * Bn + b) * G4H;
                float gi = acc[i][0] + xr[j];
                float gf = acc[i][1] + xr[Hn + j];
                float gg = acc[i][2] + xr[2 * Hn + j];
                float go = acc[i][3] + xr[3 * Hn + j];
                float cn = sigf(gf) * c0r[i] + sigf(gi) * tanhf(gg);
                float hn = sigf(go) * tanhf(cn);
                c0r[i] = cn;
                __stcg(g_dh0 + ((size_t)t * Bn + b) * Hn + j, hn);
            }
            gsync(ctr, (++phase) * gridDim.x);
        }

        // ---- phase B: layer 1 ----
        {
            float acc[2][4] = {};
            #pragma unroll 1
            for (int src = 0; src < 2; src++) {
                const float* X = (src == 0)
                    ? (g_dh0 + ((size_t)t * Bn) * Hn)
                    : ((t == 0) ? g_hb : (g_dechs + ((size_t)(t - 1) * Bn) * Hn));
                const float* W = (src == 0) ? W1x : W1h;
                for (int k0 = 0; k0 < Hn; k0 += 32) {
                    for (int i2 = tid; i2 < 512; i2 += 256) {
                        int bl = i2 >> 3, q = i2 & 7;
                        float4 v = __ldcg(reinterpret_cast<const float4*>(
                            X + (size_t)(bh * 64 + bl) * Hn + k0 + q * 4));
                        Hsm[bl * 33 + q * 4 + 0] = v.x;
                        Hsm[bl * 33 + q * 4 + 1] = v.y;
                        Hsm[bl * 33 + q * 4 + 2] = v.z;
                        Hsm[bl * 33 + q * 4 + 3] = v.w;
                    }
                    __syncthreads();
                    #pragma unroll 8
                    for (int kk = 0; kk < 32; kk++) {
                        float w0 = W[0 * 4096 + (k0 + kk) * 8 + jj];
                        float w1 = W[1 * 4096 + (k0 + kk) * 8 + jj];
                        float w2 = W[2 * 4096 + (k0 + kk) * 8 + jj];
                        float w3 = W[3 * 4096 + (k0 + kk) * 8 + jj];
                        #pragma unroll
                        for (int i = 0; i < 2; i++) {
                            float h = Hsm[(bq * 2 + i) * 33 + kk];
                            acc[i][0] += h * w0; acc[i][1] += h * w1;
                            acc[i][2] += h * w2; acc[i][3] += h * w3;
                        }
                    }
                    __syncthreads();
                }
            }
            #pragma unroll
            for (int i = 0; i < 2; i++) {
                int b = bh * 64 + bq * 2 + i;
                float gi = acc[i][0] + bias1g[0];
                float gf = acc[i][1] + bias1g[1];
                float gg = acc[i][2] + bias1g[2];
                float go = acc[i][3] + bias1g[3];
                float cn = sigf(gf) * c1r[i] + sigf(gi) * tanhf(gg);
                float hn = sigf(go) * tanhf(cn);
                c1r[i] = cn;
                __stcg(g_dechs + ((size_t)t * Bn + b) * Hn + j, hn);
            }
            if (t < Tn - 1) gsync(ctr, (++phase) * gridDim.x);
        }
    }
}

// ---------------- bridge -------------------------------------------------------
__global__ void bridge_kernel(const float* __restrict__ hW, const float* __restrict__ hb,
                              const float* __restrict__ cW, const float* __restrict__ cb)
{
    int idx = blockIdx.x * blockDim.x + threadIdx.x;
    int b = idx >> 9;
    int j = idx & (Hn - 1);
    const float* hf  = g_h1 + ((size_t)(Tn - 1) * Bn + b) * (2 * Hn);
    const float* hbk = g_h1 + (size_t)b * (2 * Hn) + Hn;
    const float* cf  = g_cfF + (size_t)b * Hn;
    const float* cbk = g_cfB + (size_t)b * Hn;
    float sh = hb[j], sc = cb[j];
    for (int k = 0; k < Hn; k++) {
        sh += hf[k]  * hW[(size_t)k * Hn + j];
        sc += cf[k]  * cW[(size_t)k * Hn + j];
    }
    for (int k = 0; k < Hn; k++) {
        sh += hbk[k] * hW[(size_t)(Hn + k) * Hn + j];
        sc += cbk[k] * cW[(size_t)(Hn + k) * Hn + j];
    }
    g_hb[idx] = tanhf(sh);
    g_cb[idx] = tanhf(sc);
}

// ---------------- host orchestration -----------------------------------------
extern "C" void kernel_launch(void* const* d_in, const int* in_sizes, int n_in,
                              void* d_out, int out_size)
{
    const int*   x       = (const int*)  d_in[0];
    const float* emb     = (const float*)d_in[1];
    const float* ef_Wx0  = (const float*)d_in[2];
    const float* ef_Wh0  = (const float*)d_in[3];
    const float* ef_b0   = (const float*)d_in[4];
    const float* ef_Wx1  = (const float*)d_in[5];
    const float* ef_Wh1  = (const float*)d_in[6];
    const float* ef_b1   = (const float*)d_in[7];
    const float* eb_Wx0  = (const float*)d_in[8];
    const float* eb_Wh0  = (const float*)d_in[9];
    const float* eb_b0   = (const float*)d_in[10];
    const float* eb_Wx1  = (const float*)d_in[11];
    const float* eb_Wh1  = (const float*)d_in[12];
    const float* eb_b1   = (const float*)d_in[13];
    const float* d_Wx0   = (const float*)d_in[14];
    const float* d_Wh0   = (const float*)d_in[15];
    const float* d_b0    = (const float*)d_in[16];
    const float* d_Wx1   = (const float*)d_in[17];
    const float* d_Wh1   = (const float*)d_in[18];
    const float* d_b1    = (const float*)d_in[19];
    const float* hproj_W = (const float*)d_in[20];
    const float* hproj_b = (const float*)d_in[21];
    const float* cproj_W = (const float*)d_in[22];
    const float* cproj_b = (const float*)d_in[23];
    const float* fc_W    = (const float*)d_in[24];
    const float* fc_b    = (const float*)d_in[25];
    float* out = (float*)d_out;

    float *e, *li, *h1, *xpF, *xpB, *dechs, *cfF, *cfB;
    unsigned* ctr;
    cudaGetSymbolAddress((void**)&e,     g_e);
    cudaGetSymbolAddress((void**)&li,    g_li);
    cudaGetSymbolAddress((void**)&h1,    g_h1);
    cudaGetSymbolAddress((void**)&xpF,   g_xpF);
    cudaGetSymbolAddress((void**)&xpB,   g_xpB);
    cudaGetSymbolAddress((void**)&dechs, g_dechs);
    cudaGetSymbolAddress((void**)&cfF,   g_cfF);
    cudaGetSymbolAddress((void**)&cfB,   g_cfB);
    cudaGetSymbolAddress((void**)&ctr,   g_ctr);

    const int ENC_SMEM = (16384 + 32 * 132) * 4;           // 82,432 B
    const int DEC_SMEM = (49152 + 64 * 33) * 4;            // 205,056 B
    cudaFuncSetAttribute(enc_scan<false>,
                         cudaFuncAttributeMaxDynamicSharedMemorySize, ENC_SMEM);
    cudaFuncSetAttribute(enc_scan<true>,
                         cudaFuncAttributeMaxDynamicSharedMemorySize, ENC_SMEM);
    cudaFuncSetAttribute(dec_scan,
                         cudaFuncAttributeMaxDynamicSharedMemorySize, DEC_SMEM);

    const dim3 gXP(G4H / 128, TBr / 128);    // (16, 512)
    const dim3 gFC(Vn / 128, TBr / 128);     // (4, 512)

    // 0) reset grid-barrier counters
    reset_bar_kernel<<<1, 32>>>();

    // 1) embedding
    embed_kernel<<<(int)(((size_t)TBr * En) / 256), 256>>>(x, emb);

    // 2) encoder layer0 (K = 256)
    gemm128<0><<<gXP, 256>>>(TBr, G4H, En, e, ef_Wx0, ef_b0, xpF);
    gemm128<0><<<gXP, 256>>>(TBr, G4H, En, e, eb_Wx0, eb_b0, xpB);
    enc_scan<false><<<NBLK, 128, ENC_SMEM>>>(xpF, xpB, ef_Wh0, eb_Wh0,
                                             li, nullptr, nullptr, ctr + 0);

    // 3) encoder layer1 (K = 1024)
    gemm128<0><<<gXP, 256>>>(TBr, G4H, 2 * Hn, li, ef_Wx1, ef_b1, xpF);
    gemm128<0><<<gXP, 256>>>(TBr, G4H, 2 * Hn, li, eb_Wx1, eb_b1, xpB);
    enc_scan<true><<<NBLK, 128, ENC_SMEM>>>(xpF, xpB, ef_Wh1, eb_Wh1,
                                            h1, cfF, cfB, ctr + 1);

    // 4) bridge
    bridge_kernel<<<BH / 256, 256>>>(hproj_W, hproj_b, cproj_W, cproj_b);

    // 5) decoder (x-part K = 256)
    gemm128<0><<<gXP, 256>>>(TBr, G4H, En, e, d_Wx0, d_b0, xpF);
    dec_scan<<<NBLK, 256, DEC_SMEM>>>(xpF, d_Wh0, d_Wx1, d_Wh1, d_b1, ctr + 2);

    // 6) FC head
    gemm128<1><<<gFC, 256>>>(TBr, Vn, Hn, dechs, fc_W, fc_b, out);
}

// round 15
// speedup vs baseline: 1.3068x; 1.3068x over previous
#include <cuda_runtime.h>
#include <math.h>
#include <stdint.h>

#define Tn 512
#define Bn 128
#define En 256
#define Hn 512
#define Vn 512
#define G4H 2048
#define TBr (Tn*Bn)     // 65536 rows (t*B + b)
#define BH  (Bn*Hn)     // 65536
#define NBLK 128

typedef unsigned long long ull;

// ---------------- packed f32x2 helpers ----------------------------------------
__device__ __forceinline__ ull dup2(float a) {
    ull r;
    asm("mov.b64 %0, {%1, %1};" : "=l"(r) : "f"(a));
    return r;
}
__device__ __forceinline__ void ffma2(ull& d, ull a, ull b) {
    asm("fma.rn.f32x2 %0, %1, %2, %0;" : "+l"(d) : "l"(a), "l"(b));
}
__device__ __forceinline__ float2 unpack2(ull v) {
    float2 r;
    asm("mov.b64 {%0, %1}, %2;" : "=f"(r.x), "=f"(r.y) : "l"(v));
    return r;
}

// ---------------- scratch (__device__ globals) --------------------------------
__device__ float g_e[(size_t)TBr * En];        // embeddings [T,B,E]
__device__ float g_li[(size_t)TBr * 2 * Hn];   // enc layer0 h history [T,B,2H]
__device__ float g_h1[(size_t)TBr * 2 * Hn];   // enc layer1 h history [T,B,2H]
__device__ float g_xpF[(size_t)TBr * G4H];     // x@Wx+bias, fwd
__device__ float g_xpB[(size_t)TBr * G4H];     // x@Wx+bias, bwd
__device__ float g_dh0[(size_t)TBr * Hn];      // decoder layer0 h history
__device__ float g_dechs[(size_t)TBr * Hn];    // decoder layer1 h history
__device__ float g_cfF[BH];                    // enc layer1 final c, fwd
__device__ float g_cfB[BH];                    // enc layer1 final c, bwd
__device__ float g_hb[BH];                     // bridge h init
__device__ float g_cb[BH];                     // bridge c init
__device__ unsigned g_ctr[4];                  // grid-barrier counters

// ---------------- grid barrier (release/acquire) ------------------------------
__device__ __forceinline__ void gsync(unsigned* ctr, unsigned target) {
    __threadfence();
    __syncthreads();
    if (threadIdx.x == 0) {
        asm volatile("red.release.gpu.global.add.u32 [%0], %1;"
                     :: "l"(ctr), "r"(1u) : "memory");
        unsigned v;
        do {
            asm volatile("ld.acquire.gpu.global.u32 %0, [%1];"
                         : "=r"(v) : "l"(ctr) : "memory");
            if (v >= target) break;
            __nanosleep(64);
        } while (true);
    }
    __syncthreads();
    __threadfence();
}

__global__ void reset_bar_kernel() {
    if (threadIdx.x < 4) g_ctr[threadIdx.x] = 0;
}

__device__ __forceinline__ float sigf(float x) { return 1.f / (1.f + expf(-x)); }

// ---------------- embedding (E = 256) -----------------------------------------
__global__ void embed_kernel(const int* __restrict__ x, const float* __restrict__ emb) {
    size_t idx = (size_t)blockIdx.x * blockDim.x + threadIdx.x;
    int r = (int)(idx >> 8);
    int c = (int)(idx & (En - 1));
    int t = r >> 7;
    int b = r & 127;
    int tok = x[b * Tn + t];
    g_e[idx] = emb[(size_t)tok * En + c];
}

// ---------------- 128x128 GEMM with packed f32x2 (kept from R14: fma 55%) ------
template<int MAP>
__global__ __launch_bounds__(256) void gemm128(
    int M, int N, int K,
    const float* __restrict__ A, const float* __restrict__ W,
    const float* __restrict__ bias, float* __restrict__ C)
{
    __shared__ float As[8][128];
    __shared__ float Ws[8][128];
    const int bm = blockIdx.y * 128;
    const int bn = blockIdx.x * 128;
    const int tid = threadIdx.x;
    const int tr = tid / 16, tc = tid % 16;

    int crow = bm + tid / 2;
    int arow;
    if (MAP == 1) { int b = crow >> 9; int t = crow & (Tn - 1); arow = t * Bn + b; }
    else          { arow = crow; }
    const float* Aptr = A + (size_t)arow * K + (tid & 1) * 4;
    const float* Wptr = W + (size_t)(tid / 32) * N + bn + (tid & 31) * 4;

    ull acc[8][4];
    #pragma unroll
    for (int i = 0; i < 8; i++)
        #pragma unroll
        for (int p = 0; p < 4; p++) acc[i][p] = 0ull;

    for (int k0 = 0; k0 < K; k0 += 8) {
        float4 a4 = *reinterpret_cast<const float4*>(Aptr + k0);
        float4 w4 = *reinterpret_cast<const float4*>(Wptr + (size_t)k0 * N);
        int ka = (tid & 1) * 4, ra = tid >> 1;
        As[ka + 0][ra] = a4.x; As[ka + 1][ra] = a4.y;
        As[ka + 2][ra] = a4.z; As[ka + 3][ra] = a4.w;
        *reinterpret_cast<float4*>(&Ws[tid / 32][(tid & 31) * 4]) = w4;
        __syncthreads();
        #pragma unroll
        for (int k = 0; k < 8; k++) {
            float4 a0 = *reinterpret_cast<float4*>(&As[k][tr * 8]);
            float4 a1 = *reinterpret_cast<float4*>(&As[k][tr * 8 + 4]);
            ulonglong2 w0 = *reinterpret_cast<ulonglong2*>(&Ws[k][tc * 8]);
            ulonglong2 w1 = *reinterpret_cast<ulonglong2*>(&Ws[k][tc * 8 + 4]);
            float av[8] = {a0.x, a0.y, a0.z, a0.w, a1.x, a1.y, a1.z, a1.w};
            ull wp[4] = {w0.x, w0.y, w1.x, w1.y};
            #pragma unroll
            for (int i = 0; i < 8; i++) {
                ull ad = dup2(av[i]);
                #pragma unroll
                for (int p = 0; p < 4; p++) ffma2(acc[i][p], ad, wp[p]);
            }
        }
        __syncthreads();
    }

    #pragma unroll
    for (int i = 0; i < 8; i++) {
        int row = bm + tr * 8 + i;
        float* Crow = C + (size_t)row * N + bn + tc * 8;
        float out[8];
        #pragma unroll
        for (int p = 0; p < 4; p++) {
            float2 v = unpack2(acc[i][p]);
            out[2 * p]     = v.x + bias[bn + tc * 8 + 2 * p];
            out[2 * p + 1] = v.y + bias[bn + tc * 8 + 2 * p + 1];
        }
        *reinterpret_cast<float4*>(Crow)     = make_float4(out[0], out[1], out[2], out[3]);
        *reinterpret_cast<float4*>(Crow + 4) = make_float4(out[4], out[5], out[6], out[7]);
    }
}

// ============ persistent encoder scan (REVERTED to R13: 256 threads) ==========
// 128 blocks: dir = bid&1, jt = bid>>1 -> 8 j's per block, all 128 b.
// c register-resident; h exchanged via fresh t-indexed history rows.
template<bool CFIN>
__global__ __launch_bounds__(256) void enc_scan(
    const float* xpF, const float* xpB,
    const float* WhF, const float* WhB,
    float* hist, float* cfF, float* cfB, unsigned* ctr)
{
    extern __shared__ float sm[];
    float* Wsm = sm;                 // 16384 floats
    float* Hsm = sm + 16384;         // 128*33 floats
    const int tid = threadIdx.x;
    const int dir = blockIdx.x & 1;
    const int jt  = blockIdx.x >> 1;
    const int jb  = jt * 8;
    const int jj  = tid & 7;
    const int bq  = tid >> 3;        // 0..31
    const int j   = jb + jj;

    const float* Wh = dir ? WhB : WhF;
    const float* xp = dir ? xpB : xpF;
    float* cf = dir ? cfB : cfF;

    for (int i = tid; i < 16384; i += 256) {
        int g = i >> 12, k = (i >> 3) & 511, j2 = i & 7;
        Wsm[i] = Wh[(size_t)k * G4H + g * Hn + jb + j2];
    }
    __syncthreads();

    float cr[4] = {0.f, 0.f, 0.f, 0.f};
    unsigned phase = 0;

    for (int t = 0; t < Tn; t++) {
        const int tcur = dir ? (Tn - 1 - t) : t;
        float acc[4][4] = {};

        if (t > 0) {
            const int tprev = dir ? (tcur + 1) : (tcur - 1);
            const float* hp = hist + ((size_t)tprev * Bn) * (2 * Hn) + dir * Hn;
            for (int k0 = 0; k0 < Hn; k0 += 32) {
                for (int i2 = tid; i2 < 1024; i2 += 256) {
                    int b = i2 >> 3, q = i2 & 7;
                    float4 v = __ldcg(reinterpret_cast<const float4*>(
                        hp + (size_t)b * (2 * Hn) + k0 + q * 4));
                    Hsm[b * 33 + q * 4 + 0] = v.x;
                    Hsm[b * 33 + q * 4 + 1] = v.y;
                    Hsm[b * 33 + q * 4 + 2] = v.z;
                    Hsm[b * 33 + q * 4 + 3] = v.w;
                }
                __syncthreads();
                #pragma unroll 8
                for (int kk = 0; kk < 32; kk++) {
                    float w0 = Wsm[0 * 4096 + (k0 + kk) * 8 + jj];
                    float w1 = Wsm[1 * 4096 + (k0 + kk) * 8 + jj];
                    float w2 = Wsm[2 * 4096 + (k0 + kk) * 8 + jj];
                    float w3 = Wsm[3 * 4096 + (k0 + kk) * 8 + jj];
                    #pragma unroll
                    for (int i = 0; i < 4; i++) {
                        float h = Hsm[(bq * 4 + i) * 33 + kk];
                        acc[i][0] += h * w0; acc[i][1] += h * w1;
                        acc[i][2] += h * w2; acc[i][3] += h * w3;
                    }
                }
                __syncthreads();
            }
        }

        #pragma unroll
        for (int i = 0; i < 4; i++) {
            int b = bq * 4 + i;
            const float* xr = xp + ((size_t)tcur * Bn + b) * G4H;
            float gi = acc[i][0] + xr[j];
            float gf = acc[i][1] + xr[Hn + j];
            float gg = acc[i][2] + xr[2 * Hn + j];
            float go = acc[i][3] + xr[3 * Hn + j];
            float cn = sigf(gf) * cr[i] + sigf(gi) * tanhf(gg);
            float hn = sigf(go) * tanhf(cn);
            cr[i] = cn;
            __stcg(hist + ((size_t)tcur * Bn + b) * (2 * Hn) + dir * Hn + j, hn);
        }
        if (t < Tn - 1) gsync(ctr, (++phase) * gridDim.x);
    }

    if (CFIN) {
        #pragma unroll
        for (int i = 0; i < 4; i++)
            cf[(size_t)(bq * 4 + i) * Hn + j] = cr[i];
    }
}

// ============ persistent decoder scan (unchanged from R13) ====================
__global__ __launch_bounds__(256) void dec_scan(
    const float* xp0, const float* Wh0, const float* Wx1,
    const float* Wh1, const float* b1, unsigned* ctr)
{
    extern __shared__ float sm[];
    float* W0  = sm;
    float* W1x = sm + 16384;
    float* W1h = sm + 32768;
    float* Hsm = sm + 49152;         // 64*33
    const int tid = threadIdx.x;
    const int bh = blockIdx.x & 1;
    const int jt = blockIdx.x >> 1;
    const int jb = jt * 8;
    const int jj = tid & 7;
    const int bq = tid >> 3;         // 0..31
    const int j  = jb + jj;

    for (int i = tid; i < 16384; i += 256) {
        int g = i >> 12, k = (i >> 3) & 511, j2 = i & 7;
        size_t off = (size_t)k * G4H + g * Hn + jb + j2;
        W0[i]  = Wh0[off];
        W1x[i] = Wx1[off];
        W1h[i] = Wh1[off];
    }
    float bias1g[4];
    #pragma unroll
    for (int g = 0; g < 4; g++) bias1g[g] = b1[g * Hn + j];
    __syncthreads();

    float c0r[2], c1r[2];
    #pragma unroll
    for (int i = 0; i < 2; i++) {
        int b = bh * 64 + bq * 2 + i;
        float cinit = g_cb[(size_t)b * Hn + j];
        c0r[i] = cinit;
        c1r[i] = cinit;
    }

    unsigned phase = 0;
    for (int t = 0; t < Tn; t++) {
        // ---- phase A: layer 0 ----
        {
            float acc[2][4] = {};
            const float* hbase = (t == 0) ? g_hb
                               : (g_dh0 + ((size_t)(t - 1) * Bn) * Hn);
            for (int k0 = 0; k0 < Hn; k0 += 32) {
                for (int i2 = tid; i2 < 512; i2 += 256) {
                    int bl = i2 >> 3, q = i2 & 7;
                    float4 v = __ldcg(reinterpret_cast<const float4*>(
                        hbase + (size_t)(bh * 64 + bl) * Hn + k0 + q * 4));
                    Hsm[bl * 33 + q * 4 + 0] = v.x;
                    Hsm[bl * 33 + q * 4 + 1] = v.y;
                    Hsm[bl * 33 + q * 4 + 2] = v.z;
                    Hsm[bl * 33 + q * 4 + 3] = v.w;
                }
                __syncthreads();
                #pragma unroll 8
                for (int kk = 0; kk < 32; kk++) {
                    float w0 = W0[0 * 4096 + (k0 + kk) * 8 + jj];
                    float w1 = W0[1 * 4096 + (k0 + kk) * 8 + jj];
                    float w2 = W0[2 * 4096 + (k0 + kk) * 8 + jj];
                    float w3 = W0[3 * 4096 + (k0 + kk) * 8 + jj];
                    #pragma unroll
                    for (int i = 0; i < 2; i++) {
                        float h = Hsm[(bq * 2 + i) * 33 + kk];
                        acc[i][0] += h * w0; acc[i][1] += h * w1;
                        acc[i][2] += h * w2; acc[i][3] += h * w3;
                    }
                }
                __syncthreads();
            }
            #pragma unroll
            for (int i = 0; i < 2; i++) {
                int b = bh * 64 + bq * 2 + i;
                const float* xr = xp0 + ((size_t)t * Bn + b) * G4H;
                float gi = acc[i][0] + xr[j];
                float gf = acc[i][1] + xr[Hn + j];
                float gg = acc[i][2] + xr[2 * Hn + j];
                float go = acc[i][3] + xr[3 * Hn + j];
                float cn = sigf(gf) * c0r[i] + sigf(gi) * tanhf(gg);
                float hn = sigf(go) * tanhf(cn);
                c0r[i] = cn;
                __stcg(g_dh0 + ((size_t)t * Bn + b) * Hn + j, hn);
            }
            gsync(ctr, (++phase) * gridDim.x);
        }

        // ---- phase B: layer 1 ----
        {
            float acc[2][4] = {};
            #pragma unroll 1
            for (int src = 0; src < 2; src++) {
                const float* X = (src == 0)
                    ? (g_dh0 + ((size_t)t * Bn) * Hn)
                    : ((t == 0) ? g_hb : (g_dechs + ((size_t)(t - 1) * Bn) * Hn));
                const float* W = (src == 0) ? W1x : W1h;
                for (int k0 = 0; k0 < Hn; k0 += 32) {
                    for (int i2 = tid; i2 < 512; i2 += 256) {
                        int bl = i2 >> 3, q = i2 & 7;
                        float4 v = __ldcg(reinterpret_cast<const float4*>(
                            X + (size_t)(bh * 64 + bl) * Hn + k0 + q * 4));
                        Hsm[bl * 33 + q * 4 + 0] = v.x;
                        Hsm[bl * 33 + q * 4 + 1] = v.y;
                        Hsm[bl * 33 + q * 4 + 2] = v.z;
                        Hsm[bl * 33 + q * 4 + 3] = v.w;
                    }
                    __syncthreads();
                    #pragma unroll 8
                    for (int kk = 0; kk < 32; kk++) {
                        float w0 = W[0 * 4096 + (k0 + kk) * 8 + jj];
                        float w1 = W[1 * 4096 + (k0 + kk) * 8 + jj];
                        float w2 = W[2 * 4096 + (k0 + kk) * 8 + jj];
                        float w3 = W[3 * 4096 + (k0 + kk) * 8 + jj];
                        #pragma unroll
                        for (int i = 0; i < 2; i++) {
                            float h = Hsm[(bq * 2 + i) * 33 + kk];
                            acc[i][0] += h * w0; acc[i][1] += h * w1;
                            acc[i][2] += h * w2; acc[i][3] += h * w3;
                        }
                    }
                    __syncthreads();
                }
            }
            #pragma unroll
            for (int i = 0; i < 2; i++) {
                int b = bh * 64 + bq * 2 + i;
                float gi = acc[i][0] + bias1g[0];
                float gf = acc[i][1] + bias1g[1];
                float gg = acc[i][2] + bias1g[2];
                float go = acc[i][3] + bias1g[3];
                float cn = sigf(gf) * c1r[i] + sigf(gi) * tanhf(gg);
                float hn = sigf(go) * tanhf(cn);
                c1r[i] = cn;
                __stcg(g_dechs + ((size_t)t * Bn + b) * Hn + j, hn);
            }
            if (t < Tn - 1) gsync(ctr, (++phase) * gridDim.x);
        }
    }
}

// ---------------- bridge -------------------------------------------------------
__global__ void bridge_kernel(const float* __restrict__ hW, const float* __restrict__ hb,
                              const float* __restrict__ cW, const float* __restrict__ cb)
{
    int idx = blockIdx.x * blockDim.x + threadIdx.x;
    int b = idx >> 9;
    int j = idx & (Hn - 1);
    const float* hf  = g_h1 + ((size_t)(Tn - 1) * Bn + b) * (2 * Hn);
    const float* hbk = g_h1 + (size_t)b * (2 * Hn) + Hn;
    const float* cf  = g_cfF + (size_t)b * Hn;
    const float* cbk = g_cfB + (size_t)b * Hn;
    float sh = hb[j], sc = cb[j];
    for (int k = 0; k < Hn; k++) {
        sh += hf[k]  * hW[(size_t)k * Hn + j];
        sc += cf[k]  * cW[(size_t)k * Hn + j];
    }
    for (int k = 0; k < Hn; k++) {
        sh += hbk[k] * hW[(size_t)(Hn + k) * Hn + j];
        sc += cbk[k] * cW[(size_t)(Hn + k) * Hn + j];
    }
    g_hb[idx] = tanhf(sh);
    g_cb[idx] = tanhf(sc);
}

// ---------------- host orchestration -----------------------------------------
extern "C" void kernel_launch(void* const* d_in, const int* in_sizes, int n_in,
                              void* d_out, int out_size)
{
    const int*   x       = (const int*)  d_in[0];
    const float* emb     = (const float*)d_in[1];
    const float* ef_Wx0  = (const float*)d_in[2];
    const float* ef_Wh0  = (const float*)d_in[3];
    const float* ef_b0   = (const float*)d_in[4];
    const float* ef_Wx1  = (const float*)d_in[5];
    const float* ef_Wh1  = (const float*)d_in[6];
    const float* ef_b1   = (const float*)d_in[7];
    const float* eb_Wx0  = (const float*)d_in[8];
    const float* eb_Wh0  = (const float*)d_in[9];
    const float* eb_b0   = (const float*)d_in[10];
    const float* eb_Wx1  = (const float*)d_in[11];
    const float* eb_Wh1  = (const float*)d_in[12];
    const float* eb_b1   = (const float*)d_in[13];
    const float* d_Wx0   = (const float*)d_in[14];
    const float* d_Wh0   = (const float*)d_in[15];
    const float* d_b0    = (const float*)d_in[16];
    const float* d_Wx1   = (const float*)d_in[17];
    const float* d_Wh1   = (const float*)d_in[18];
    const float* d_b1    = (const float*)d_in[19];
    const float* hproj_W = (const float*)d_in[20];
    const float* hproj_b = (const float*)d_in[21];
    const float* cproj_W = (const float*)d_in[22];
    const float* cproj_b = (const float*)d_in[23];
    const float* fc_W    = (const float*)d_in[24];
    const float* fc_b    = (const float*)d_in[25];
    float* out = (float*)d_out;

    float *e, *li, *h1, *xpF, *xpB, *dechs, *cfF, *cfB;
    unsigned* ctr;
    cudaGetSymbolAddress((void**)&e,     g_e);
    cudaGetSymbolAddress((void**)&li,    g_li);
    cudaGetSymbolAddress((void**)&h1,    g_h1);
    cudaGetSymbolAddress((void**)&xpF,   g_xpF);
    cudaGetSymbolAddress((void**)&xpB,   g_xpB);
    cudaGetSymbolAddress((void**)&dechs, g_dechs);
    cudaGetSymbolAddress((void**)&cfF,   g_cfF);
    cudaGetSymbolAddress((void**)&cfB,   g_cfB);
    cudaGetSymbolAddress((void**)&ctr,   g_ctr);

    const int ENC_SMEM = (16384 + 128 * 33) * 4;           // 82,432 B
    const int DEC_SMEM = (49152 + 64 * 33) * 4;            // 205,056 B
    cudaFuncSetAttribute(enc_scan<false>,
                         cudaFuncAttributeMaxDynamicSharedMemorySize, ENC_SMEM);
    cudaFuncSetAttribute(enc_scan<true>,
                         cudaFuncAttributeMaxDynamicSharedMemorySize, ENC_SMEM);
    cudaFuncSetAttribute(dec_scan,
                         cudaFuncAttributeMaxDynamicSharedMemorySize, DEC_SMEM);

    const dim3 gXP(G4H / 128, TBr / 128);    // (16, 512)
    const dim3 gFC(Vn / 128, TBr / 128);     // (4, 512)

    // 0) reset grid-barrier counters
    reset_bar_kernel<<<1, 32>>>();

    // 1) embedding
    embed_kernel<<<(int)(((size_t)TBr * En) / 256), 256>>>(x, emb);

    // 2) encoder layer0 (K = 256)
    gemm128<0><<<gXP, 256>>>(TBr, G4H, En, e, ef_Wx0, ef_b0, xpF);
    gemm128<0><<<gXP, 256>>>(TBr, G4H, En, e, eb_Wx0, eb_b0, xpB);
    enc_scan<false><<<NBLK, 256, ENC_SMEM>>>(xpF, xpB, ef_Wh0, eb_Wh0,
                                             li, nullptr, nullptr, ctr + 0);

    // 3) encoder layer1 (K = 1024)
    gemm128<0><<<gXP, 256>>>(TBr, G4H, 2 * Hn, li, ef_Wx1, ef_b1, xpF);
    gemm128<0><<<gXP, 256>>>(TBr, G4H, 2 * Hn, li, eb_Wx1, eb_b1, xpB);
    enc_scan<true><<<NBLK, 256, ENC_SMEM>>>(xpF, xpB, ef_Wh1, eb_Wh1,
                                            h1, cfF, cfB, ctr + 1);

    // 4) bridge
    bridge_kernel<<<BH / 256, 256>>>(hproj_W, hproj_b, cproj_W, cproj_b);

    // 5) decoder (x-part K = 256)
    gemm128<0><<<gXP, 256>>>(TBr, G4H, En, e, d_Wx0, d_b0, xpF);
    dec_scan<<<NBLK, 256, DEC_SMEM>>>(xpF, d_Wh0, d_Wx1, d_Wh1, d_b1, ctr + 2);

    // 6) FC head
    gemm128<1><<<gFC, 256>>>(TBr, Vn, Hn, dechs, fc_W, fc_b, out);
}